// round 15
// baseline (speedup 1.0000x reference)
#include <cuda_runtime.h>
#include <cuda_fp16.h>
#include <cstdint>

#define NMESH 10242
#define NGRID 65160
#define NEDGES 195480
#define DD 512
#define OUTD 471

#define THREADS 128     // 4 warps, 2x2, warp tile 64x64
#define MT 128
#define NT 128
#define KCH 32
#define HSTRIDE 40      // smem row stride in fp16 units

// ---- smem layout (bytes) ----
#define SA_OFF 0
#define SB_OFF 20480
#define SBIAS_OFF 40960
#define SI0_OFF 41472
#define SI1_OFF 41984
#define SIDX_OFF 42496
#define SMEM_BYTES 43008

// ---- scratch ----
__device__ float  g_e[(size_t)NEDGES * DD];
__device__ __half g_h16[(size_t)NEDGES * DD];
__device__ float  g_agg[(size_t)NGRID * DD];
__device__ __half g_nh16[(size_t)NGRID * DD];
__device__ __half g_g2_16[(size_t)NGRID * DD];
__device__ __half g_oh16[(size_t)NGRID * DD];
__device__ __half g_mesh16[(size_t)NMESH * DD];
__device__ __half g_grid16[(size_t)NGRID * DD];
__device__ __half g_wh[2600448];

#define WT_EMB1   0
#define WT_EDGE0  262144
#define WT_EDGE1  1048576
#define WT_NODE0  1310720
#define WT_NODE1  1835008
#define WT_OUT0   2097152
#define WT_OUT1   2359296

__device__ __forceinline__ float silu_f(float v) { return v / (1.0f + __expf(-v)); }

__device__ __forceinline__ void mma_f16(float (&d)[4], const uint32_t (&a)[4],
                                        const uint32_t (&b)[2]) {
    asm volatile(
        "mma.sync.aligned.m16n8k16.row.col.f32.f16.f16.f32 "
        "{%0,%1,%2,%3}, {%4,%5,%6,%7}, {%8,%9}, {%0,%1,%2,%3};"
        : "+f"(d[0]), "+f"(d[1]), "+f"(d[2]), "+f"(d[3])
        : "r"(a[0]), "r"(a[1]), "r"(a[2]), "r"(a[3]), "r"(b[0]), "r"(b[1]));
}

__device__ __forceinline__ void ldsm_x4(uint32_t (&r)[4], uint32_t addr) {
    asm volatile("ldmatrix.sync.aligned.m8n8.x4.shared.b16 {%0,%1,%2,%3}, [%4];"
        : "=r"(r[0]), "=r"(r[1]), "=r"(r[2]), "=r"(r[3]) : "r"(addr));
}

__device__ __forceinline__ void cp16(uint32_t dst, const void* src) {
    asm volatile("cp.async.cg.shared.global [%0], [%1], 16;" :: "r"(dst), "l"(src) : "memory");
}
__device__ __forceinline__ void cp16z(uint32_t dst, const void* src, int sz) {
    asm volatile("cp.async.cg.shared.global [%0], [%1], 16, %2;"
                 :: "r"(dst), "l"(src), "r"(sz) : "memory");
}
#define CP_COMMIT() asm volatile("cp.async.commit_group;" ::: "memory")
#define CP_WAIT0()  asm volatile("cp.async.wait_group 0;" ::: "memory")

// ======================= prologue kernels =======================
__global__ void k_prep_w(const float* __restrict__ emb_w1, const float* __restrict__ edge_w0,
                         const float* __restrict__ edge_w1, const float* __restrict__ node_w0,
                         const float* __restrict__ node_w1, const float* __restrict__ out_w0,
                         const float* __restrict__ out_w1, __half* __restrict__ gwh) {
    int t = blockIdx.x;
    const float* in; __half* out; int K, N, tk;
    if (t < 256)       { in = emb_w1;  out = gwh + WT_EMB1;  K = 512;  N = 512; t -= 0;    tk = 16; }
    else if (t < 1024) { in = edge_w0; out = gwh + WT_EDGE0; K = 1536; N = 512; t -= 256;  tk = 48; }
    else if (t < 1280) { in = edge_w1; out = gwh + WT_EDGE1; K = 512;  N = 512; t -= 1024; tk = 16; }
    else if (t < 1792) { in = node_w0; out = gwh + WT_NODE0; K = 1024; N = 512; t -= 1280; tk = 32; }
    else if (t < 2048) { in = node_w1; out = gwh + WT_NODE1; K = 512;  N = 512; t -= 1792; tk = 16; }
    else if (t < 2304) { in = out_w0;  out = gwh + WT_OUT0;  K = 512;  N = 512; t -= 2048; tk = 16; }
    else               { in = out_w1;  out = gwh + WT_OUT1;  K = 512;  N = 471; t -= 2304; tk = 16; }
    int k0 = (t % tk) * 32, n0 = (t / tk) * 32;
    __shared__ float tt[32][33];
#pragma unroll
    for (int i = 0; i < 4; i++) {
        int k = k0 + threadIdx.y + i * 8;
        int n = n0 + threadIdx.x;
        tt[threadIdx.y + i * 8][threadIdx.x] = (k < K && n < N) ? in[(size_t)k * N + n] : 0.f;
    }
    __syncthreads();
#pragma unroll
    for (int i = 0; i < 4; i++) {
        int n = n0 + threadIdx.y + i * 8;
        int k = k0 + threadIdx.x;
        if (n < N && k < K)
            out[(size_t)n * K + k] = __float2half_rn(tt[threadIdx.x][threadIdx.y + i * 8]);
    }
}

__global__ void k_prep_act(const float* __restrict__ mesh, const float* __restrict__ grid,
                           __half* __restrict__ m16, __half* __restrict__ g16) {
    const long long nm = (long long)NMESH * DD;
    const long long total = nm + (long long)NGRID * DD;
    long long i = ((long long)blockIdx.x * blockDim.x + threadIdx.x) * 4;
    long long stride = (long long)gridDim.x * blockDim.x * 4;
    for (; i < total; i += stride) {
        const float* src; __half* dst; long long off;
        if (i < nm) { src = mesh; dst = m16; off = i; }
        else        { src = grid; dst = g16; off = i - nm; }
        float4 v = *(const float4*)(src + off);
        __half2 h0 = __floats2half2_rn(v.x, v.y);
        __half2 h1 = __floats2half2_rn(v.z, v.w);
        *(uint2*)(dst + off) = make_uint2(*(uint32_t*)&h0, *(uint32_t*)&h1);
    }
}

__global__ void k_emb_l1(const float* __restrict__ attrs,
                         const float* __restrict__ w0,
                         const float* __restrict__ b0) {
    long long idx = (long long)blockIdx.x * blockDim.x + threadIdx.x;
    if (idx >= (long long)NEDGES * DD) return;
    int i = (int)(idx / DD);
    int j = (int)(idx % DD);
    float v = b0[j];
    v += attrs[i * 4 + 0] * w0[0 * DD + j];
    v += attrs[i * 4 + 1] * w0[1 * DD + j];
    v += attrs[i * 4 + 2] * w0[2 * DD + j];
    v += attrs[i * 4 + 3] * w0[3 * DD + j];
    g_h16[idx] = __float2half_rn(silu_f(v));
}

__global__ void k_zero(float* __restrict__ p, long long n) {
    long long i = (long long)blockIdx.x * blockDim.x + threadIdx.x;
    long long stride = (long long)gridDim.x * blockDim.x;
    for (; i < n; i += stride) p[i] = 0.0f;
}

// ======================= fp16 mma.sync GEMM (64x64 warp tiles) =======================
// AMODE 0: plain A0 (A16). 1: [mesh16[g0]|grid16[g1]|g_e(f32)] K=1536. 2: [grid16|agg] K=1024.
template <int AMODE, bool A16, bool C16, bool SILU_, bool RESID_, bool SCATTER_, bool STORE_>
__global__ void __launch_bounds__(THREADS)
k_mma(const void* __restrict__ A0, const void* __restrict__ A1,
      const void* __restrict__ A2,
      const int* __restrict__ gidx0, const int* __restrict__ gidx1,
      const __half* __restrict__ Wh, const float* __restrict__ bias,
      const float* __restrict__ resid,
      void* __restrict__ C,
      float* __restrict__ scat, const int* __restrict__ scat_idx,
      int M, int N, int K) {
    extern __shared__ char smraw[];
    __half* sA = (__half*)(smraw + SA_OFF);
    __half* sB = (__half*)(smraw + SB_OFF);
    float* sbias = (float*)(smraw + SBIAS_OFF);
    int* sI0 = (int*)(smraw + SI0_OFF);
    int* sI1 = (int*)(smraw + SI1_OFF);
    int* sIdx = (int*)(smraw + SIDX_OFF);

    const int tid = threadIdx.x;
    const int lane = tid & 31;
    const int wid = tid >> 5;
    const int m0 = blockIdx.y * MT;
    const int n0 = blockIdx.x * NT;

    {
        sbias[tid] = (n0 + tid < N) ? bias[n0 + tid] : 0.0f;
        int gr = m0 + tid; if (gr >= M) gr = M - 1;
        if (AMODE == 1) { sI0[tid] = gidx0[gr]; sI1[tid] = gidx1[gr]; }
        if (SCATTER_) sIdx[tid] = scat_idx[gr];
    }
    __syncthreads();

    const int arow = tid >> 2;        // 0..31 (+32j, j=0..3)
    const int au = tid & 3;           // 16B unit (8 halves / 8 floats' worth)

    const uint32_t sA_u32 = (uint32_t)__cvta_generic_to_shared(sA);
    const uint32_t sB_u32 = (uint32_t)__cvta_generic_to_shared(sB);

    float4 ra[4][2];   // fp32 staging (8 floats per row-unit)

    auto issueAB = [&](int chn) -> bool {
        const int kc0 = chn * KCH;
        const int buf = chn & 1;
        const uint32_t dAbase = sA_u32 + buf * (128 * HSTRIDE) * 2;
        const uint32_t dBbase = sB_u32 + buf * (128 * HSTRIDE) * 2;
        bool f32seg;
        if (AMODE == 1)      f32seg = (kc0 >= 2 * DD);
        else if (AMODE == 2) f32seg = (kc0 >= DD);
        else                 f32seg = !A16;
        if (!f32seg) {
#pragma unroll
            for (int j = 0; j < 4; j++) {
                int row = arow + j * 32;
                int gr = m0 + row; if (gr >= M) gr = M - 1;
                const __half* src;
                if (AMODE == 0) {
                    src = (const __half*)A0 + (size_t)gr * K + kc0;
                } else if (AMODE == 1) {
                    src = (kc0 < DD) ? (const __half*)A0 + (size_t)sI0[row] * DD + kc0
                                     : (const __half*)A1 + (size_t)sI1[row] * DD + (kc0 - DD);
                } else {
                    src = (const __half*)A0 + (size_t)gr * DD + kc0;
                }
                cp16(dAbase + (row * HSTRIDE + au * 8) * 2, src + au * 8);
            }
        } else {
#pragma unroll
            for (int j = 0; j < 4; j++) {
                int row = arow + j * 32;
                int gr = m0 + row; if (gr >= M) gr = M - 1;
                const float* src;
                if (AMODE == 1)      src = (const float*)A2 + (size_t)gr * DD + (kc0 - 2 * DD);
                else if (AMODE == 2) src = (const float*)A1 + (size_t)gr * DD + (kc0 - DD);
                else                 src = (const float*)A0 + (size_t)gr * K + kc0;
                ra[j][0] = *(const float4*)(src + au * 8);
                ra[j][1] = *(const float4*)(src + au * 8 + 4);
            }
        }
#pragma unroll
        for (int j = 0; j < 4; j++) {
            int row = arow + j * 32;       // B rows: same mapping
            int n = n0 + row;
            int nn = (n < N) ? n : (N - 1);
            const __half* src = Wh + (size_t)nn * K + kc0 + au * 8;
            cp16z(dBbase + (row * HSTRIDE + au * 8) * 2, src, (n < N) ? 16 : 0);
        }
        CP_COMMIT();
        return f32seg;
    };
    auto stsA32 = [&](int chn) {
        const int buf = chn & 1;
        __half* dA = sA + buf * (128 * HSTRIDE);
#pragma unroll
        for (int j = 0; j < 4; j++) {
            int row = arow + j * 32;
            __half2 h0 = __floats2half2_rn(ra[j][0].x, ra[j][0].y);
            __half2 h1 = __floats2half2_rn(ra[j][0].z, ra[j][0].w);
            __half2 h2 = __floats2half2_rn(ra[j][1].x, ra[j][1].y);
            __half2 h3 = __floats2half2_rn(ra[j][1].z, ra[j][1].w);
            uint4 o = make_uint4(*(uint32_t*)&h0, *(uint32_t*)&h1,
                                 *(uint32_t*)&h2, *(uint32_t*)&h3);
            *(uint4*)(dA + row * HSTRIDE + au * 8) = o;
        }
    };

    float acc[4][8][4] = {};
    const int wm = wid >> 1;          // 0..1
    const int wn = wid & 1;           // 0..1
    const int r = lane >> 2;
    const int c = lane & 3;

    const uint32_t a_lane_off = (uint32_t)((wm * 64 + (lane & 15)) * HSTRIDE + ((lane >> 4) & 1) * 8);
    const uint32_t b_lane_off = (uint32_t)((wn * 64 + ((lane >> 4) & 1) * 8 + (lane & 7)) * HSTRIDE
                                           + ((lane >> 3) & 1) * 8);

    const int nch = K / KCH;
    {
        bool f32p = issueAB(0);
        if (f32p) stsA32(0);
        CP_WAIT0();
        __syncthreads();
    }

    for (int ch = 0; ch < nch; ch++) {
        const int buf = ch & 1;
        bool f32n = false;
        if (ch + 1 < nch) f32n = issueAB(ch + 1);

        const uint32_t aBase = sA_u32 + (buf * (128 * HSTRIDE) + a_lane_off) * 2;
        const uint32_t bBase = sB_u32 + (buf * (128 * HSTRIDE) + b_lane_off) * 2;
#pragma unroll
        for (int kk = 0; kk < 2; kk++) {
            const int kb = kk * 16;
            uint32_t af[4][4], bf[8][2];
#pragma unroll
            for (int mf = 0; mf < 4; mf++)
                ldsm_x4(af[mf], aBase + (mf * 16 * HSTRIDE + kb) * 2);
#pragma unroll
            for (int g = 0; g < 4; g++) {
                uint32_t bq[4];
                ldsm_x4(bq, bBase + (g * 16 * HSTRIDE + kb) * 2);
                bf[2 * g][0] = bq[0]; bf[2 * g][1] = bq[1];
                bf[2 * g + 1][0] = bq[2]; bf[2 * g + 1][1] = bq[3];
            }
#pragma unroll
            for (int mf = 0; mf < 4; mf++)
#pragma unroll
                for (int nf = 0; nf < 8; nf++)
                    mma_f16(acc[mf][nf], af[mf], bf[nf]);
        }
        if (f32n) stsA32(ch + 1);
        CP_WAIT0();
        __syncthreads();
    }

    // ---- epilogue ----
#pragma unroll
    for (int mf = 0; mf < 4; mf++) {
        const int lr0 = wm * 64 + mf * 16 + r;
        const int lr1 = lr0 + 8;
        const int row0 = m0 + lr0;
        const int row1 = m0 + lr1;
        int sidx0 = 0, sidx1 = 0;
        if (SCATTER_) { sidx0 = sIdx[lr0]; sidx1 = sIdx[lr1]; }
#pragma unroll
        for (int nf = 0; nf < 8; nf++) {
            const int lc = wn * 64 + nf * 8 + c * 2;
            const int n = n0 + lc;
#pragma unroll
            for (int half_ = 0; half_ < 2; half_++) {
                const int row = half_ ? row1 : row0;
                const int sidx = half_ ? sidx1 : sidx0;
                if (row >= M) continue;
#pragma unroll
                for (int jj = 0; jj < 2; jj++) {
                    const int nn = n + jj;
                    if (nn >= N) continue;
                    float v = acc[mf][nf][half_ * 2 + jj] + sbias[lc + jj];
                    if (SILU_) v = silu_f(v);
                    if (RESID_) v += resid[(size_t)row * DD + nn];
                    if (STORE_) {
                        if (C16) ((__half*)C)[(size_t)row * N + nn] = __float2half_rn(v);
                        else     ((float*)C)[(size_t)row * N + nn] = v;
                    }
                    if (SCATTER_) atomicAdd(&scat[(size_t)sidx * DD + nn], v);
                }
            }
        }
    }
}

// ======================= host =======================
extern "C" void kernel_launch(void* const* d_in, const int* in_sizes, int n_in,
                              void* d_out, int out_size) {
    const float* mesh    = (const float*)d_in[0];
    const float* grid    = (const float*)d_in[1];
    const float* attrs   = (const float*)d_in[2];
    const int*   esrc    = (const int*)d_in[3];
    const int*   edst    = (const int*)d_in[4];
    const float* emb_w0  = (const float*)d_in[5];
    const float* emb_b0  = (const float*)d_in[6];
    const float* emb_w1  = (const float*)d_in[7];
    const float* emb_b1  = (const float*)d_in[8];
    const float* edge_w0 = (const float*)d_in[9];
    const float* edge_b0 = (const float*)d_in[10];
    const float* edge_w1 = (const float*)d_in[11];
    const float* edge_b1 = (const float*)d_in[12];
    const float* node_w0 = (const float*)d_in[13];
    const float* node_b0 = (const float*)d_in[14];
    const float* node_w1 = (const float*)d_in[15];
    const float* node_b1 = (const float*)d_in[16];
    const float* out_w0  = (const float*)d_in[17];
    const float* out_b0  = (const float*)d_in[18];
    const float* out_w1  = (const float*)d_in[19];
    const float* out_b1  = (const float*)d_in[20];
    float* out = (float*)d_out;

    float *ge, *gagg;
    __half *gh16, *gnh16, *gg216, *goh16, *gmesh16, *ggrid16, *gwh;
    cudaGetSymbolAddress((void**)&ge, g_e);
    cudaGetSymbolAddress((void**)&gh16, g_h16);
    cudaGetSymbolAddress((void**)&gagg, g_agg);
    cudaGetSymbolAddress((void**)&gnh16, g_nh16);
    cudaGetSymbolAddress((void**)&gg216, g_g2_16);
    cudaGetSymbolAddress((void**)&goh16, g_oh16);
    cudaGetSymbolAddress((void**)&gmesh16, g_mesh16);
    cudaGetSymbolAddress((void**)&ggrid16, g_grid16);
    cudaGetSymbolAddress((void**)&gwh, g_wh);

    cudaFuncSetAttribute(k_mma<0, true,  false, false, false, false, true>,  cudaFuncAttributeMaxDynamicSharedMemorySize, SMEM_BYTES);
    cudaFuncSetAttribute(k_mma<1, false, true,  true,  false, false, true>,  cudaFuncAttributeMaxDynamicSharedMemorySize, SMEM_BYTES);
    cudaFuncSetAttribute(k_mma<0, true,  false, false, true,  true,  false>, cudaFuncAttributeMaxDynamicSharedMemorySize, SMEM_BYTES);
    cudaFuncSetAttribute(k_mma<2, false, true,  true,  false, false, true>,  cudaFuncAttributeMaxDynamicSharedMemorySize, SMEM_BYTES);
    cudaFuncSetAttribute(k_mma<0, true,  true,  false, true,  false, true>,  cudaFuncAttributeMaxDynamicSharedMemorySize, SMEM_BYTES);
    cudaFuncSetAttribute(k_mma<0, true,  true,  true,  false, false, true>,  cudaFuncAttributeMaxDynamicSharedMemorySize, SMEM_BYTES);

    const int TE = (NEDGES + MT - 1) / MT;  // 1528
    const int TG = (NGRID + MT - 1) / MT;   // 510
    const int CN = (DD + NT - 1) / NT;      // 4
    const int CO = (OUTD + NT - 1) / NT;    // 4

    k_prep_w<<<2544, dim3(32, 8)>>>(emb_w1, edge_w0, edge_w1, node_w0, node_w1,
                                    out_w0, out_w1, gwh);
    k_prep_act<<<2048, 256>>>(mesh, grid, gmesh16, ggrid16);
    {
        long long n = (long long)NEDGES * DD;
        k_emb_l1<<<(unsigned)((n + 255) / 256), 256>>>(attrs, emb_w0, emb_b0);
    }
    // emb L2 -> g_e (fp32)
    k_mma<0, true, false, false, false, false, true><<<dim3(CN, TE), THREADS, SMEM_BYTES>>>(
        gh16, nullptr, nullptr, nullptr, nullptr, gwh + WT_EMB1, emb_b1,
        nullptr, ge, nullptr, nullptr, NEDGES, DD, DD);
    k_zero<<<2048, 256>>>(gagg, (long long)NGRID * DD);
    // edge L1 gather-concat
    k_mma<1, false, true, true, false, false, true><<<dim3(CN, TE), THREADS, SMEM_BYTES>>>(
        gmesh16, ggrid16, ge, esrc, edst, gwh + WT_EDGE0, edge_b0,
        nullptr, gh16, nullptr, nullptr, NEDGES, DD, 3 * DD);
    // edge L2 + residual + scatter
    k_mma<0, true, false, false, true, true, false><<<dim3(CN, TE), THREADS, SMEM_BYTES>>>(
        gh16, nullptr, nullptr, nullptr, nullptr, gwh + WT_EDGE1, edge_b1,
        ge, nullptr, gagg, edst, NEDGES, DD, DD);
    // node L1
    k_mma<2, false, true, true, false, false, true><<<dim3(CN, TG), THREADS, SMEM_BYTES>>>(
        ggrid16, gagg, nullptr, nullptr, nullptr, gwh + WT_NODE0, node_b0,
        nullptr, gnh16, nullptr, nullptr, NGRID, DD, 2 * DD);
    // node L2 + residual
    k_mma<0, true, true, false, true, false, true><<<dim3(CN, TG), THREADS, SMEM_BYTES>>>(
        gnh16, nullptr, nullptr, nullptr, nullptr, gwh + WT_NODE1, node_b1,
        grid, gg216, nullptr, nullptr, NGRID, DD, DD);
    // out L1
    k_mma<0, true, true, true, false, false, true><<<dim3(CN, TG), THREADS, SMEM_BYTES>>>(
        gg216, nullptr, nullptr, nullptr, nullptr, gwh + WT_OUT0, out_b0,
        nullptr, goh16, nullptr, nullptr, NGRID, DD, DD);
    // out L2 (N=471)
    k_mma<0, true, false, false, false, false, true><<<dim3(CO, TG), THREADS, SMEM_BYTES>>>(
        goh16, nullptr, nullptr, nullptr, nullptr, gwh + WT_OUT1, out_b1,
        nullptr, out, nullptr, nullptr, NGRID, OUTD, DD);
}

// round 16
// speedup vs baseline: 1.1686x; 1.1686x over previous
#include <cuda_runtime.h>
#include <cuda_fp16.h>
#include <cstdint>

#define NMESH 10242
#define NGRID 65160
#define NEDGES 195480
#define DD 512
#define OUTD 471

#define THREADS 256
#define MT 128
#define NT 128
#define KCH 32
#define HSTRIDE 40      // smem row stride in fp16 units

// ---- smem layout (bytes) ----
#define SA_OFF 0
#define SB_OFF 20480
#define SBIAS_OFF 40960
#define SI0_OFF 41472
#define SI1_OFF 41984
#define SIDX_OFF 42496
#define SMEM_BYTES 43008

// ---- scratch ----
__device__ float  g_e[(size_t)NEDGES * DD];       // fp32 e (residual source)
__device__ __half g_e16[(size_t)NEDGES * DD];     // fp16 e (GEMM A input)
__device__ __half g_h16[(size_t)NEDGES * DD];     // hidden (emb hidden, edge hidden)
__device__ float  g_agg[(size_t)NGRID * DD];
__device__ __half g_nh16[(size_t)NGRID * DD];
__device__ __half g_g2_16[(size_t)NGRID * DD];
__device__ __half g_oh16[(size_t)NGRID * DD];
__device__ __half g_mesh16[(size_t)NMESH * DD];
__device__ __half g_grid16[(size_t)NGRID * DD];
__device__ float  g_pm[(size_t)NMESH * DD];       // mesh @ W_m (fp32)
__device__ float  g_pg[(size_t)NGRID * DD];       // grid @ W_g (fp32)
__device__ float  g_zb[DD];                       // zero bias
__device__ __half g_wh[2600448];

#define WT_EMB1   0
#define WT_E0M    262144
#define WT_E0G    524288
#define WT_E0E    786432
#define WT_EDGE1  1048576
#define WT_NODE0  1310720
#define WT_NODE1  1835008
#define WT_OUT0   2097152
#define WT_OUT1   2359296

__device__ __forceinline__ float silu_f(float v) { return v / (1.0f + __expf(-v)); }

__device__ __forceinline__ void mma_f16(float (&d)[4], const uint32_t (&a)[4],
                                        const uint32_t (&b)[2]) {
    asm volatile(
        "mma.sync.aligned.m16n8k16.row.col.f32.f16.f16.f32 "
        "{%0,%1,%2,%3}, {%4,%5,%6,%7}, {%8,%9}, {%0,%1,%2,%3};"
        : "+f"(d[0]), "+f"(d[1]), "+f"(d[2]), "+f"(d[3])
        : "r"(a[0]), "r"(a[1]), "r"(a[2]), "r"(a[3]), "r"(b[0]), "r"(b[1]));
}

__device__ __forceinline__ void ldsm_x4(uint32_t (&r)[4], uint32_t addr) {
    asm volatile("ldmatrix.sync.aligned.m8n8.x4.shared.b16 {%0,%1,%2,%3}, [%4];"
        : "=r"(r[0]), "=r"(r[1]), "=r"(r[2]), "=r"(r[3]) : "r"(addr));
}

__device__ __forceinline__ void cp8(uint32_t dst, const void* src) {
    asm volatile("cp.async.ca.shared.global [%0], [%1], 8;" :: "r"(dst), "l"(src) : "memory");
}
__device__ __forceinline__ void cp16z(uint32_t dst, const void* src, int sz) {
    asm volatile("cp.async.cg.shared.global [%0], [%1], 16, %2;"
                 :: "r"(dst), "l"(src), "r"(sz) : "memory");
}
#define CP_COMMIT() asm volatile("cp.async.commit_group;" ::: "memory")
#define CP_WAIT0()  asm volatile("cp.async.wait_group 0;" ::: "memory")

// ======================= prologue kernels =======================
// All weight transposes (edge_w0 split into 3 parts of 512 rows each).
__global__ void k_prep_w(const float* __restrict__ emb_w1, const float* __restrict__ edge_w0,
                         const float* __restrict__ edge_w1, const float* __restrict__ node_w0,
                         const float* __restrict__ node_w1, const float* __restrict__ out_w0,
                         const float* __restrict__ out_w1, __half* __restrict__ gwh) {
    int t = blockIdx.x;
    const float* in; __half* out; int K = 512, N = 512, tk = 16;
    if (t < 256)       { in = emb_w1;                    out = gwh + WT_EMB1;  t -= 0; }
    else if (t < 512)  { in = edge_w0;                   out = gwh + WT_E0M;   t -= 256; }
    else if (t < 768)  { in = edge_w0 + 262144;          out = gwh + WT_E0G;   t -= 512; }
    else if (t < 1024) { in = edge_w0 + 524288;          out = gwh + WT_E0E;   t -= 768; }
    else if (t < 1280) { in = edge_w1;                   out = gwh + WT_EDGE1; t -= 1024; }
    else if (t < 1792) { in = node_w0; K = 1024; tk = 32; out = gwh + WT_NODE0; t -= 1280; }
    else if (t < 2048) { in = node_w1;                   out = gwh + WT_NODE1; t -= 1792; }
    else if (t < 2304) { in = out_w0;                    out = gwh + WT_OUT0;  t -= 2048; }
    else               { in = out_w1; N = 471;           out = gwh + WT_OUT1;  t -= 2304; }
    int k0 = (t % tk) * 32, n0 = (t / tk) * 32;
    __shared__ float tt[32][33];
#pragma unroll
    for (int i = 0; i < 4; i++) {
        int k = k0 + threadIdx.y + i * 8;
        int n = n0 + threadIdx.x;
        tt[threadIdx.y + i * 8][threadIdx.x] = (k < K && n < N) ? in[(size_t)k * N + n] : 0.f;
    }
    __syncthreads();
#pragma unroll
    for (int i = 0; i < 4; i++) {
        int n = n0 + threadIdx.y + i * 8;
        int k = k0 + threadIdx.x;
        if (n < N && k < K)
            out[(size_t)n * K + k] = __float2half_rn(tt[threadIdx.x][threadIdx.y + i * 8]);
    }
}

__global__ void k_prep_act(const float* __restrict__ mesh, const float* __restrict__ grid,
                           __half* __restrict__ m16, __half* __restrict__ g16,
                           float* __restrict__ zb) {
    if (blockIdx.x == 0 && threadIdx.x < 256) {
        zb[threadIdx.x] = 0.0f; zb[threadIdx.x + 256] = 0.0f;
    }
    const long long nm = (long long)NMESH * DD;
    const long long total = nm + (long long)NGRID * DD;
    long long i = ((long long)blockIdx.x * blockDim.x + threadIdx.x) * 4;
    long long stride = (long long)gridDim.x * blockDim.x * 4;
    for (; i < total; i += stride) {
        const float* src; __half* dst; long long off;
        if (i < nm) { src = mesh; dst = m16; off = i; }
        else        { src = grid; dst = g16; off = i - nm; }
        float4 v = *(const float4*)(src + off);
        __half2 h0 = __floats2half2_rn(v.x, v.y);
        __half2 h1 = __floats2half2_rn(v.z, v.w);
        *(uint2*)(dst + off) = make_uint2(*(uint32_t*)&h0, *(uint32_t*)&h1);
    }
}

__global__ void k_emb_l1(const float* __restrict__ attrs,
                         const float* __restrict__ w0,
                         const float* __restrict__ b0) {
    long long idx = (long long)blockIdx.x * blockDim.x + threadIdx.x;
    if (idx >= (long long)NEDGES * DD) return;
    int i = (int)(idx / DD);
    int j = (int)(idx % DD);
    float v = b0[j];
    v += attrs[i * 4 + 0] * w0[0 * DD + j];
    v += attrs[i * 4 + 1] * w0[1 * DD + j];
    v += attrs[i * 4 + 2] * w0[2 * DD + j];
    v += attrs[i * 4 + 3] * w0[3 * DD + j];
    g_h16[idx] = __float2half_rn(silu_f(v));
}

__global__ void k_zero(float* __restrict__ p, long long n) {
    long long i = (long long)blockIdx.x * blockDim.x + threadIdx.x;
    long long stride = (long long)gridDim.x * blockDim.x;
    for (; i < n; i += stride) p[i] = 0.0f;
}

// ======================= fp16 mma.sync GEMM =======================
// AMODE 0: plain A0 (A16). 2: [grid16|agg(f32)] K=1024.
// GADD_: epilogue adds A1[gidx0[row]][n] + A2[gidx1[row]][n] (fp32 tables).
// CBOTH_: store fp32 to C AND fp16 to C2.
template <int AMODE, bool A16, bool C16, bool SILU_, bool RESID_, bool SCATTER_,
          bool STORE_, bool GADD_, bool CBOTH_>
__global__ void __launch_bounds__(THREADS)
k_mma(const void* __restrict__ A0, const void* __restrict__ A1,
      const void* __restrict__ A2,
      const int* __restrict__ gidx0, const int* __restrict__ gidx1,
      const __half* __restrict__ Wh, const float* __restrict__ bias,
      const float* __restrict__ resid,
      void* __restrict__ C, __half* __restrict__ C2,
      float* __restrict__ scat, const int* __restrict__ scat_idx,
      int M, int N, int K) {
    extern __shared__ char smraw[];
    __half* sA = (__half*)(smraw + SA_OFF);
    __half* sB = (__half*)(smraw + SB_OFF);
    float* sbias = (float*)(smraw + SBIAS_OFF);
    int* sI0 = (int*)(smraw + SI0_OFF);
    int* sI1 = (int*)(smraw + SI1_OFF);
    int* sIdx = (int*)(smraw + SIDX_OFF);

    const int tid = threadIdx.x;
    const int lane = tid & 31;
    const int wid = tid >> 5;
    const int m0 = blockIdx.y * MT;
    const int n0 = blockIdx.x * NT;

    if (tid < 128) {
        sbias[tid] = (n0 + tid < N) ? bias[n0 + tid] : 0.0f;
        int gr = m0 + tid; if (gr >= M) gr = M - 1;
        if (GADD_) { sI0[tid] = gidx0[gr]; sI1[tid] = gidx1[gr]; }
        if (SCATTER_) sIdx[tid] = scat_idx[gr];
    }
    __syncthreads();

    const int arow = tid >> 3;        // 0..31
    const int aq = tid & 7;           // 0..7
    const int brow = tid >> 2;        // 0..63
    const int bu = tid & 3;           // 0..3

    const uint32_t sA_u32 = (uint32_t)__cvta_generic_to_shared(sA);
    const uint32_t sB_u32 = (uint32_t)__cvta_generic_to_shared(sB);

    float4 ra[4];   // fp32 staging

    auto issueAB = [&](int chn) -> bool {
        const int kc0 = chn * KCH;
        const int buf = chn & 1;
        const uint32_t dAbase = sA_u32 + buf * (128 * HSTRIDE) * 2;
        const uint32_t dBbase = sB_u32 + buf * (128 * HSTRIDE) * 2;
        bool f32seg;
        if (AMODE == 2) f32seg = (kc0 >= DD);
        else            f32seg = !A16;
        if (!f32seg) {
#pragma unroll
            for (int j = 0; j < 4; j++) {
                int row = arow + j * 32;
                int gr = m0 + row; if (gr >= M) gr = M - 1;
                const __half* src;
                if (AMODE == 0) src = (const __half*)A0 + (size_t)gr * K + kc0;
                else            src = (const __half*)A0 + (size_t)gr * DD + kc0;
                cp8(dAbase + (row * HSTRIDE + aq * 4) * 2, src + aq * 4);
            }
        } else {
#pragma unroll
            for (int j = 0; j < 4; j++) {
                int row = arow + j * 32;
                int gr = m0 + row; if (gr >= M) gr = M - 1;
                const float* src;
                if (AMODE == 2) src = (const float*)A1 + (size_t)gr * DD + (kc0 - DD);
                else            src = (const float*)A0 + (size_t)gr * K + kc0;
                ra[j] = *(const float4*)(src + aq * 4);
            }
        }
#pragma unroll
        for (int j = 0; j < 2; j++) {
            int row = brow + j * 64;
            int n = n0 + row;
            int nn = (n < N) ? n : (N - 1);
            const __half* src = Wh + (size_t)nn * K + kc0 + bu * 8;
            cp16z(dBbase + (row * HSTRIDE + bu * 8) * 2, src, (n < N) ? 16 : 0);
        }
        CP_COMMIT();
        return f32seg;
    };
    auto stsA32 = [&](int chn) {
        const int buf = chn & 1;
        __half* dA = sA + buf * (128 * HSTRIDE);
#pragma unroll
        for (int j = 0; j < 4; j++) {
            int row = arow + j * 32;
            float4 v = ra[j];
            __half2 h0 = __floats2half2_rn(v.x, v.y);
            __half2 h1 = __floats2half2_rn(v.z, v.w);
            *(uint2*)(dA + row * HSTRIDE + aq * 4) = make_uint2(*(uint32_t*)&h0, *(uint32_t*)&h1);
        }
    };

    float acc[4][4][4] = {};
    const int wm = wid >> 2;
    const int wn = wid & 3;
    const int r = lane >> 2;
    const int c = lane & 3;

    const uint32_t a_lane_off = (uint32_t)((wm * 64 + (lane & 15)) * HSTRIDE + ((lane >> 4) & 1) * 8);
    const uint32_t b_lane_off = (uint32_t)((wn * 32 + ((lane >> 4) & 1) * 8 + (lane & 7)) * HSTRIDE
                                           + ((lane >> 3) & 1) * 8);

    const int nch = K / KCH;
    {
        bool f32p = issueAB(0);
        if (f32p) stsA32(0);
        CP_WAIT0();
        __syncthreads();
    }

    for (int ch = 0; ch < nch; ch++) {
        const int buf = ch & 1;
        bool f32n = false;
        if (ch + 1 < nch) f32n = issueAB(ch + 1);

        const uint32_t aBase = sA_u32 + (buf * (128 * HSTRIDE) + a_lane_off) * 2;
        const uint32_t bBase = sB_u32 + (buf * (128 * HSTRIDE) + b_lane_off) * 2;
#pragma unroll
        for (int kk = 0; kk < 2; kk++) {
            const int kb = kk * 16;
            uint32_t af[4][4], bf[4][2];
#pragma unroll
            for (int mf = 0; mf < 4; mf++)
                ldsm_x4(af[mf], aBase + (mf * 16 * HSTRIDE + kb) * 2);
#pragma unroll
            for (int g = 0; g < 2; g++) {
                uint32_t bq[4];
                ldsm_x4(bq, bBase + (g * 16 * HSTRIDE + kb) * 2);
                bf[2 * g][0] = bq[0]; bf[2 * g][1] = bq[1];
                bf[2 * g + 1][0] = bq[2]; bf[2 * g + 1][1] = bq[3];
            }
#pragma unroll
            for (int mf = 0; mf < 4; mf++)
#pragma unroll
                for (int nf = 0; nf < 4; nf++)
                    mma_f16(acc[mf][nf], af[mf], bf[nf]);
        }
        if (f32n) stsA32(ch + 1);
        CP_WAIT0();
        __syncthreads();
    }

    // ---- epilogue ----
#pragma unroll
    for (int mf = 0; mf < 4; mf++) {
        const int lr0 = wm * 64 + mf * 16 + r;
        const int lr1 = lr0 + 8;
        const int row0 = m0 + lr0;
        const int row1 = m0 + lr1;
        int sidx0 = 0, sidx1 = 0;
        if (SCATTER_) { sidx0 = sIdx[lr0]; sidx1 = sIdx[lr1]; }
        int gA0 = 0, gA1 = 0, gB0 = 0, gB1 = 0;
        if (GADD_) { gA0 = sI0[lr0]; gA1 = sI0[lr1]; gB0 = sI1[lr0]; gB1 = sI1[lr1]; }
#pragma unroll
        for (int nf = 0; nf < 4; nf++) {
            const int lc = wn * 32 + nf * 8 + c * 2;
            const int n = n0 + lc;
#pragma unroll
            for (int half_ = 0; half_ < 2; half_++) {
                const int row = half_ ? row1 : row0;
                const int sidx = half_ ? sidx1 : sidx0;
                const int gA = half_ ? gA1 : gA0;
                const int gB = half_ ? gB1 : gB0;
                if (row >= M) continue;
#pragma unroll
                for (int jj = 0; jj < 2; jj++) {
                    const int nn = n + jj;
                    if (nn >= N) continue;
                    float v = acc[mf][nf][half_ * 2 + jj] + sbias[lc + jj];
                    if (GADD_)
                        v += ((const float*)A1)[(size_t)gA * DD + nn]
                           + ((const float*)A2)[(size_t)gB * DD + nn];
                    if (SILU_) v = silu_f(v);
                    if (RESID_) v += resid[(size_t)row * DD + nn];
                    if (STORE_) {
                        if (C16) ((__half*)C)[(size_t)row * N + nn] = __float2half_rn(v);
                        else     ((float*)C)[(size_t)row * N + nn] = v;
                    }
                    if (CBOTH_) C2[(size_t)row * N + nn] = __float2half_rn(v);
                    if (SCATTER_) atomicAdd(&scat[(size_t)sidx * DD + nn], v);
                }
            }
        }
    }
}

// ======================= host =======================
extern "C" void kernel_launch(void* const* d_in, const int* in_sizes, int n_in,
                              void* d_out, int out_size) {
    const float* mesh    = (const float*)d_in[0];
    const float* grid    = (const float*)d_in[1];
    const float* attrs   = (const float*)d_in[2];
    const int*   esrc    = (const int*)d_in[3];
    const int*   edst    = (const int*)d_in[4];
    const float* emb_w0  = (const float*)d_in[5];
    const float* emb_b0  = (const float*)d_in[6];
    const float* emb_w1  = (const float*)d_in[7];
    const float* emb_b1  = (const float*)d_in[8];
    const float* edge_w0 = (const float*)d_in[9];
    const float* edge_b0 = (const float*)d_in[10];
    const float* edge_w1 = (const float*)d_in[11];
    const float* edge_b1 = (const float*)d_in[12];
    const float* node_w0 = (const float*)d_in[13];
    const float* node_b0 = (const float*)d_in[14];
    const float* node_w1 = (const float*)d_in[15];
    const float* node_b1 = (const float*)d_in[16];
    const float* out_w0  = (const float*)d_in[17];
    const float* out_b0  = (const float*)d_in[18];
    const float* out_w1  = (const float*)d_in[19];
    const float* out_b1  = (const float*)d_in[20];
    float* out = (float*)d_out;

    float *ge, *gagg, *gpm, *gpg, *gzb;
    __half *ge16, *gh16, *gnh16, *gg216, *goh16, *gmesh16, *ggrid16, *gwh;
    cudaGetSymbolAddress((void**)&ge, g_e);
    cudaGetSymbolAddress((void**)&ge16, g_e16);
    cudaGetSymbolAddress((void**)&gh16, g_h16);
    cudaGetSymbolAddress((void**)&gagg, g_agg);
    cudaGetSymbolAddress((void**)&gnh16, g_nh16);
    cudaGetSymbolAddress((void**)&gg216, g_g2_16);
    cudaGetSymbolAddress((void**)&goh16, g_oh16);
    cudaGetSymbolAddress((void**)&gmesh16, g_mesh16);
    cudaGetSymbolAddress((void**)&ggrid16, g_grid16);
    cudaGetSymbolAddress((void**)&gpm, g_pm);
    cudaGetSymbolAddress((void**)&gpg, g_pg);
    cudaGetSymbolAddress((void**)&gzb, g_zb);
    cudaGetSymbolAddress((void**)&gwh, g_wh);

    // unique instantiations
    cudaFuncSetAttribute(k_mma<0, true,  false, false, false, false, true,  false, false>, cudaFuncAttributeMaxDynamicSharedMemorySize, SMEM_BYTES);
    cudaFuncSetAttribute(k_mma<0, true,  false, false, false, false, true,  false, true >, cudaFuncAttributeMaxDynamicSharedMemorySize, SMEM_BYTES);
    cudaFuncSetAttribute(k_mma<0, true,  true,  true,  false, false, true,  true,  false>, cudaFuncAttributeMaxDynamicSharedMemorySize, SMEM_BYTES);
    cudaFuncSetAttribute(k_mma<0, true,  false, false, true,  true,  false, false, false>, cudaFuncAttributeMaxDynamicSharedMemorySize, SMEM_BYTES);
    cudaFuncSetAttribute(k_mma<2, false, true,  true,  false, false, true,  false, false>, cudaFuncAttributeMaxDynamicSharedMemorySize, SMEM_BYTES);
    cudaFuncSetAttribute(k_mma<0, true,  true,  false, true,  false, true,  false, false>, cudaFuncAttributeMaxDynamicSharedMemorySize, SMEM_BYTES);
    cudaFuncSetAttribute(k_mma<0, true,  true,  true,  false, false, true,  false, false>, cudaFuncAttributeMaxDynamicSharedMemorySize, SMEM_BYTES);

    const int TE = (NEDGES + MT - 1) / MT;  // 1528
    const int TG = (NGRID + MT - 1) / MT;   // 510
    const int TMM = (NMESH + MT - 1) / MT;  // 81
    const int CN = DD / NT;                 // 4
    const int CO = (OUTD + NT - 1) / NT;    // 4

    k_prep_w<<<2544, dim3(32, 8)>>>(emb_w1, edge_w0, edge_w1, node_w0, node_w1,
                                    out_w0, out_w1, gwh);
    k_prep_act<<<2048, 256>>>(mesh, grid, gmesh16, ggrid16, gzb);
    {
        long long n = (long long)NEDGES * DD;
        k_emb_l1<<<(unsigned)((n + 255) / 256), 256>>>(attrs, emb_w0, emb_b0);
    }
    // emb L2: e = g_h16 @ emb_w1 + b1 -> g_e (fp32) AND g_e16 (fp16)
    k_mma<0, true, false, false, false, false, true, false, true><<<dim3(CN, TE), THREADS, SMEM_BYTES>>>(
        gh16, nullptr, nullptr, nullptr, nullptr, gwh + WT_EMB1, emb_b1,
        nullptr, ge, ge16, nullptr, nullptr, NEDGES, DD, DD);
    // P_m = mesh16 @ W_m (zero bias)
    k_mma<0, true, false, false, false, false, true, false, false><<<dim3(CN, TMM), THREADS, SMEM_BYTES>>>(
        gmesh16, nullptr, nullptr, nullptr, nullptr, gwh + WT_E0M, gzb,
        nullptr, gpm, nullptr, nullptr, nullptr, NMESH, DD, DD);
    // P_g = grid16 @ W_g (zero bias)
    k_mma<0, true, false, false, false, false, true, false, false><<<dim3(CN, TG), THREADS, SMEM_BYTES>>>(
        ggrid16, nullptr, nullptr, nullptr, nullptr, gwh + WT_E0G, gzb,
        nullptr, gpg, nullptr, nullptr, nullptr, NGRID, DD, DD);
    k_zero<<<2048, 256>>>(gagg, (long long)NGRID * DD);
    // edge L1 (decomposed): g_h16 = silu(e @ W_e + P_m[src] + P_g[dst] + b0)
    k_mma<0, true, true, true, false, false, true, true, false><<<dim3(CN, TE), THREADS, SMEM_BYTES>>>(
        ge16, gpm, gpg, esrc, edst, gwh + WT_E0E, edge_b0,
        nullptr, gh16, nullptr, nullptr, nullptr, NEDGES, DD, DD);
    // edge L2 + residual + scatter: agg[dst] += g_e + g_h16 @ edge_w1 + b1
    k_mma<0, true, false, false, true, true, false, false, false><<<dim3(CN, TE), THREADS, SMEM_BYTES>>>(
        gh16, nullptr, nullptr, nullptr, nullptr, gwh + WT_EDGE1, edge_b1,
        ge, nullptr, nullptr, gagg, edst, NEDGES, DD, DD);
    // node L1: g_nh16 = silu([grid16|agg] @ node_w0 + b0)
    k_mma<2, false, true, true, false, false, true, false, false><<<dim3(CN, TG), THREADS, SMEM_BYTES>>>(
        ggrid16, gagg, nullptr, nullptr, nullptr, gwh + WT_NODE0, node_b0,
        nullptr, gnh16, nullptr, nullptr, nullptr, NGRID, DD, 2 * DD);
    // node L2 + residual(fp32 grid)
    k_mma<0, true, true, false, true, false, true, false, false><<<dim3(CN, TG), THREADS, SMEM_BYTES>>>(
        gnh16, nullptr, nullptr, nullptr, nullptr, gwh + WT_NODE1, node_b1,
        grid, gg216, nullptr, nullptr, nullptr, NGRID, DD, DD);
    // out L1
    k_mma<0, true, true, true, false, false, true, false, false><<<dim3(CN, TG), THREADS, SMEM_BYTES>>>(
        gg216, nullptr, nullptr, nullptr, nullptr, gwh + WT_OUT0, out_b0,
        nullptr, goh16, nullptr, nullptr, nullptr, NGRID, DD, DD);
    // out L2 (N=471)
    k_mma<0, true, false, false, false, false, true, false, false><<<dim3(CO, TG), THREADS, SMEM_BYTES>>>(
        goh16, nullptr, nullptr, nullptr, nullptr, gwh + WT_OUT1, out_b1,
        nullptr, out, nullptr, nullptr, nullptr, NGRID, OUTD, DD);
}